// round 5
// baseline (speedup 1.0000x reference)
#include <cuda_runtime.h>
#include <cuda_bf16.h>

// Problem constants (from reference): B=32, M=32768, D=128, R=64, W=2R+1=129
#define RB_B 32
#define RB_M 32768
#define RB_D 128
#define RB_W 129

// Layout:
//   ring_tns:      [B, M, D] f32   (d_in[0])
//   write_vec_tns: [B, D]    f32   (d_in[1])
//   weights_tns:   [B, W]    f32   (d_in[2])
//   erase:         [B]       f32   (d_in[3])
//   write_gate:    [B]       f32   (d_in[4])
//   idx_tns:       [B, W]    i32   (d_in[5])  -- idx[b,j] = (start[b]+j) % M
//   out:           [B, M, D] f32
//
// out[b,m,:] = ring[b,m,:] unless (m - start[b]) mod M < W, in which case
//   off = (m - start[b]) mod M; w = weights[b,off]
//   out = ring * (1 - erase[b]*w) + write_gate[b]*w*write_vec[b,:]
//
// Pure HBM-bound copy with a ~0.4% row-fraction update fused in.

__global__ __launch_bounds__(256) void ring_update_kernel(
    const float4* __restrict__ ring4,     // B*M*D/4 float4
    const float4* __restrict__ wvec4,     // B*D/4 float4
    const float*  __restrict__ weights,   // B*W
    const float*  __restrict__ erase,     // B
    const float*  __restrict__ wgate,     // B
    const int*    __restrict__ idx,       // B*W
    float4*       __restrict__ out4)
{
    // Each thread: one float4 (16B) of one row.
    // vec index layout: vec = ((b*M + m) * (D/4)) + d4
    const int D4 = RB_D / 4;                       // 32
    long long i = (long long)blockIdx.x * blockDim.x + threadIdx.x;
    // total = B*M*D4 = 32*32768*32 = 33,554,432 -> fits in 32-bit but keep ll for addr
    int vec = (int)i;

    int d4  = vec & (D4 - 1);           // vec % 32
    int row = vec >> 5;                 // vec / 32   -> b*M + m
    int m   = row & (RB_M - 1);         // row % M
    int b   = row >> 15;                // row / M

    float4 cur = ring4[vec];

    // window start for this batch (idx[b,0]); broadcast, L1-resident
    int start = __ldg(&idx[b * RB_W]);
    int off = (m - start) & (RB_M - 1);

    if (off < RB_W) {
        float w = __ldg(&weights[b * RB_W + off]);
        float e = __ldg(&erase[b]);
        float g = __ldg(&wgate[b]);
        float keep = 1.0f - e * w;
        float add  = g * w;
        float4 wv = __ldg(&wvec4[b * D4 + d4]);
        cur.x = cur.x * keep + add * wv.x;
        cur.y = cur.y * keep + add * wv.y;
        cur.z = cur.z * keep + add * wv.z;
        cur.w = cur.w * keep + add * wv.w;
    }

    out4[vec] = cur;
}

extern "C" void kernel_launch(void* const* d_in, const int* in_sizes, int n_in,
                              void* d_out, int out_size)
{
    const float4* ring4   = (const float4*)d_in[0];
    const float4* wvec4   = (const float4*)d_in[1];
    const float*  weights = (const float*)d_in[2];
    const float*  erase   = (const float*)d_in[3];
    const float*  wgate   = (const float*)d_in[4];
    const int*    idx     = (const int*)d_in[5];
    float4*       out4    = (float4*)d_out;

    const long long total = (long long)RB_B * RB_M * (RB_D / 4);   // 33,554,432
    const int threads = 256;
    const int blocks = (int)((total + threads - 1) / threads);     // 131072

    ring_update_kernel<<<blocks, threads>>>(ring4, wvec4, weights, erase, wgate, idx, out4);
}

// round 6
// speedup vs baseline: 1.0053x; 1.0053x over previous
#include <cuda_runtime.h>
#include <cuda_bf16.h>

// Problem constants: B=32, M=32768, D=128, R=64, W=129
#define RB_B 32
#define RB_M 32768
#define RB_D 128
#define RB_W 129

// out[b,m,:] = ring[b,m,:] unless off=(m-start[b]) mod M < W:
//   w = weights[b,off]; out = ring*(1-erase[b]*w) + write_gate[b]*w*write_vec[b,:]
//
// HBM-bound copy (512MB R + 512MB W compulsory). This version raises MLP:
// 4 independent LDG.128 per thread, front-batched, with streaming cache
// hints (no reuse of the big stream; scalars stay in L1 via __ldg).

__global__ __launch_bounds__(256) void ring_update_kernel(
    const float4* __restrict__ ring4,     // B*M*D/4 float4
    const float4* __restrict__ wvec4,     // B*D/4 float4
    const float*  __restrict__ weights,   // B*W
    const float*  __restrict__ erase,     // B
    const float*  __restrict__ wgate,     // B
    const int*    __restrict__ idx,       // B*W
    float4*       __restrict__ out4)
{
    const int D4 = RB_D / 4;  // 32

    // Block covers 4*256 = 1024 consecutive float4s (= 32 full rows).
    int g = blockIdx.x * 1024 + threadIdx.x;

    int    vec[4];
    float4 cur[4];

    // Front-batched independent loads: MLP_p1 = 4
#pragma unroll
    for (int k = 0; k < 4; k++) {
        vec[k] = g + k * 256;
        cur[k] = __ldcs(&ring4[vec[k]]);
    }

#pragma unroll
    for (int k = 0; k < 4; k++) {
        int v   = vec[k];
        int d4  = v & (D4 - 1);        // v % 32
        int row = v >> 5;              // b*M + m
        int m   = row & (RB_M - 1);
        int b   = row >> 15;

        int start = __ldg(&idx[b * RB_W]);      // broadcast, L1-resident
        int off   = (m - start) & (RB_M - 1);

        if (off < RB_W) {
            float w = __ldg(&weights[b * RB_W + off]);
            float e = __ldg(&erase[b]);
            float gt = __ldg(&wgate[b]);
            float keep = 1.0f - e * w;
            float add  = gt * w;
            float4 wv = __ldg(&wvec4[b * D4 + d4]);
            cur[k].x = cur[k].x * keep + add * wv.x;
            cur[k].y = cur[k].y * keep + add * wv.y;
            cur[k].z = cur[k].z * keep + add * wv.z;
            cur[k].w = cur[k].w * keep + add * wv.w;
        }
    }

#pragma unroll
    for (int k = 0; k < 4; k++) {
        __stcs(&out4[vec[k]], cur[k]);
    }
}

extern "C" void kernel_launch(void* const* d_in, const int* in_sizes, int n_in,
                              void* d_out, int out_size)
{
    const float4* ring4   = (const float4*)d_in[0];
    const float4* wvec4   = (const float4*)d_in[1];
    const float*  weights = (const float*)d_in[2];
    const float*  erase   = (const float*)d_in[3];
    const float*  wgate   = (const float*)d_in[4];
    const int*    idx     = (const int*)d_in[5];
    float4*       out4    = (float4*)d_out;

    const long long total = (long long)RB_B * RB_M * (RB_D / 4);   // 33,554,432 float4
    const int threads = 256;
    const int per_block = threads * 4;                              // 1024 float4
    const int blocks = (int)(total / per_block);                    // 32768 (exact)

    ring_update_kernel<<<blocks, threads>>>(ring4, wvec4, weights, erase, wgate, idx, out4);
}